// round 14
// baseline (speedup 1.0000x reference)
#include <cuda_runtime.h>
#include <cuda_bf16.h>

#define BB 4
#define SEQ 2048
#define DMODEL 512
#define HEADS 8
#define DH 64
#define INNER 512
#define QKVW 1536   // 3 * INNER
#define SCALE 0.125f
#define INV_TAU (1.0f / 50.0f)
#define LN_EPS 1e-5f
#define NROWS (BB * HEADS * SEQ)     // 65536 attention rows
#define KTILES (SEQ / 128)           // 16 score tiles per row

// ---- static scratch (no allocations allowed) ----
__device__ float g_qkv [(size_t)BB * SEQ * QKVW];   // [b, n, 3*inner]
__device__ float g_av  [(size_t)BB * SEQ * INNER];  // attention output, [b, n, inner]
__device__ float g_u   [(size_t)BB * SEQ * DMODEL]; // unify output (pre-LN)
__device__ float g_psum[(size_t)NROWS * KTILES];    // per-(row, ktile) exp sums
__device__ float g_inv [(size_t)NROWS];             // 1 / rowsum

// ---------------------------------------------------------------------------
// helpers: bf16 split + pack, mma.m16n8k16 bf16 f32-acc
// ---------------------------------------------------------------------------
__device__ __forceinline__ unsigned pack2(float lo_elem, float hi_elem) {
    // u32 with lo_elem in low 16 bits, hi_elem in high 16 bits
    __nv_bfloat162 t = __floats2bfloat162_rn(lo_elem, hi_elem);
    return *reinterpret_cast<unsigned*>(&t);
}
__device__ __forceinline__ float bhi(float x) {
    return __bfloat162float(__float2bfloat16(x));
}
__device__ __forceinline__ void mma_bf16(float* d, const unsigned* a, const unsigned* b) {
    asm volatile(
        "mma.sync.aligned.m16n8k16.row.col.f32.bf16.bf16.f32 "
        "{%0,%1,%2,%3}, {%4,%5,%6,%7}, {%8,%9}, {%0,%1,%2,%3};\n"
        : "+f"(d[0]), "+f"(d[1]), "+f"(d[2]), "+f"(d[3])
        : "r"(a[0]), "r"(a[1]), "r"(a[2]), "r"(a[3]), "r"(b[0]), "r"(b[1]));
}

// strides (in u32 words) chosen for conflict-free fragment loads
#define QH_STR 36    // A tiles: [row][k/2], bank = 4g+tg -> 32 distinct
#define KP_STR 136   // scores B: [kp][n(128)], bank = 8tg+g -> 32 distinct
#define VP_STR 72    // pv B:     [kp][n(64)],  bank = 8tg+g -> 32 distinct

#define SC_SMEM_BYTES ((128*QH_STR*2 + 32*KP_STR*2) * 4 + 256 * 4)
#define PV_SMEM_BYTES ((128*QH_STR*2 + 32*VP_STR*2) * 4)

// ============================================================================
// Generic NN SGEMM (fp32): C[M,N] = A[M,K] @ B[K,N] (+bias). 128x128x8 tile,
// 256 threads, 8x8 microtile, double-buffered. (qkv + unify)
// ============================================================================
__global__ __launch_bounds__(256) void sgemm_nn(
    const float* __restrict__ A, const float* __restrict__ Bm,
    const float* __restrict__ bias, float* __restrict__ C,
    int M, int N, int K)
{
    __shared__ float As[2][8][128];
    __shared__ float Bs[2][8][128];
    const int tid  = threadIdx.x;
    const int row0 = blockIdx.y * 128;
    const int col0 = blockIdx.x * 128;

    const int lr  = tid >> 1;
    const int lc4 = (tid & 1) * 4;
    const int br  = tid >> 5;
    const int bc4 = (tid & 31) * 4;
    const int m0  = (tid >> 4) * 8;
    const int n0  = (tid & 15) * 8;

    const float* Aptr = A + (size_t)(row0 + lr) * K + lc4;
    const float* Bptr = Bm + (size_t)br * N + col0 + bc4;

    float acc[8][8];
#pragma unroll
    for (int i = 0; i < 8; i++)
#pragma unroll
        for (int j = 0; j < 8; j++) acc[i][j] = 0.f;

    float4 a_r = *(const float4*)(Aptr);
    float4 b_r = *(const float4*)(Bptr);
    As[0][lc4 + 0][lr] = a_r.x; As[0][lc4 + 1][lr] = a_r.y;
    As[0][lc4 + 2][lr] = a_r.z; As[0][lc4 + 3][lr] = a_r.w;
    *(float4*)&Bs[0][br][bc4] = b_r;
    __syncthreads();

    int buf = 0;
    for (int k0 = 0; k0 < K; k0 += 8) {
        const bool has_next = (k0 + 8 < K);
        if (has_next) {
            a_r = *(const float4*)(Aptr + k0 + 8);
            b_r = *(const float4*)(Bptr + (size_t)(k0 + 8) * N);
        }
#pragma unroll
        for (int kk = 0; kk < 8; kk++) {
            float a[8], bv[8];
            *(float4*)&a[0]  = *(const float4*)&As[buf][kk][m0];
            *(float4*)&a[4]  = *(const float4*)&As[buf][kk][m0 + 4];
            *(float4*)&bv[0] = *(const float4*)&Bs[buf][kk][n0];
            *(float4*)&bv[4] = *(const float4*)&Bs[buf][kk][n0 + 4];
#pragma unroll
            for (int i = 0; i < 8; i++)
#pragma unroll
                for (int j = 0; j < 8; j++) acc[i][j] += a[i] * bv[j];
        }
        if (has_next) {
            const int nb = buf ^ 1;
            As[nb][lc4 + 0][lr] = a_r.x; As[nb][lc4 + 1][lr] = a_r.y;
            As[nb][lc4 + 2][lr] = a_r.z; As[nb][lc4 + 3][lr] = a_r.w;
            *(float4*)&Bs[nb][br][bc4] = b_r;
            __syncthreads();
            buf = nb;
        }
    }

    float bb[8];
#pragma unroll
    for (int j = 0; j < 8; j++) bb[j] = bias ? bias[col0 + n0 + j] : 0.f;

#pragma unroll
    for (int i = 0; i < 8; i++) {
        float* cp = C + (size_t)(row0 + m0 + i) * N + col0 + n0;
        float4 o0, o1;
        o0.x = acc[i][0] + bb[0]; o0.y = acc[i][1] + bb[1];
        o0.z = acc[i][2] + bb[2]; o0.w = acc[i][3] + bb[3];
        o1.x = acc[i][4] + bb[4]; o1.y = acc[i][5] + bb[5];
        o1.z = acc[i][6] + bb[6]; o1.w = acc[i][7] + bb[7];
        *(float4*)cp       = o0;
        *(float4*)(cp + 4) = o1;
    }
}

// ============================================================================
// Scores (tensor cores, bf16x3 split): e[q,k] = exp((Q.K)*scale + exp(-k/tau)).
// 128x128 tile per block, 256 threads = 8 warps (4x2). d=64 resident in smem.
// Writes e (streaming) into attn region + per-(row,ktile) partial sums.
// ============================================================================
__global__ __launch_bounds__(256) void scores_tc(float* __restrict__ attn)
{
    extern __shared__ __align__(16) unsigned dsm[];
    unsigned* Qh = dsm;                        // [128][QH_STR]
    unsigned* Ql = Qh + 128 * QH_STR;
    unsigned* Kh = Ql + 128 * QH_STR;          // [32][KP_STR] packed k-pairs
    unsigned* Kl = Kh + 32 * KP_STR;
    float* rowpart = (float*)(Kl + 32 * KP_STR); // [2][128]

    const int tid = threadIdx.x;
    const int bh  = blockIdx.z;
    const int b   = bh >> 3;
    const int h   = bh & 7;
    const int qt  = blockIdx.y * 128;
    const int kt  = blockIdx.x * 128;

    // ---- load + split Q[128x64] (A layout) and K[128x64] (packed B layout)
    {
        const int row = tid >> 1, hs = tid & 1;   // hs: which 32-k half
        const float* Qg = g_qkv + (size_t)b * SEQ * QKVW + h * DH
                          + (size_t)(qt + row) * QKVW + hs * 32;
        const float* Kg = g_qkv + (size_t)b * SEQ * QKVW + INNER + h * DH
                          + (size_t)(kt + row) * QKVW + hs * 32;
#pragma unroll
        for (int j = 0; j < 8; j++) {
            float4 q = *(const float4*)(Qg + j * 4);
            float qhx = bhi(q.x), qhy = bhi(q.y), qhz = bhi(q.z), qhw = bhi(q.w);
            int qi = row * QH_STR + hs * 16 + j * 2;
            Qh[qi + 0] = pack2(qhx, qhy);
            Qh[qi + 1] = pack2(qhz, qhw);
            Ql[qi + 0] = pack2(q.x - qhx, q.y - qhy);
            Ql[qi + 1] = pack2(q.z - qhz, q.w - qhw);

            float4 k4 = *(const float4*)(Kg + j * 4);
            float khx = bhi(k4.x), khy = bhi(k4.y), khz = bhi(k4.z), khw = bhi(k4.w);
            int kp = hs * 16 + j * 2;             // k/2 index
            Kh[(kp + 0) * KP_STR + row] = pack2(khx, khy);
            Kh[(kp + 1) * KP_STR + row] = pack2(khz, khw);
            Kl[(kp + 0) * KP_STR + row] = pack2(k4.x - khx, k4.y - khy);
            Kl[(kp + 1) * KP_STR + row] = pack2(k4.z - khz, k4.w - khw);
        }
    }

    const int lane = tid & 31, wid = tid >> 5;
    const int wm = wid >> 1, wn = wid & 1;
    const int g = lane >> 2, tg = lane & 3;

    // decay bias for this thread's columns
    float2 dec2[8];
#pragma unroll
    for (int nt = 0; nt < 8; nt++) {
        int kcol = kt + wn * 64 + nt * 8 + tg * 2;
        dec2[nt].x = expf(-(float)kcol * INV_TAU);
        dec2[nt].y = expf(-(float)(kcol + 1) * INV_TAU);
    }

    float acc[2][8][4];
#pragma unroll
    for (int mt = 0; mt < 2; mt++)
#pragma unroll
        for (int nt = 0; nt < 8; nt++)
#pragma unroll
            for (int c = 0; c < 4; c++) acc[mt][nt][c] = 0.f;

    __syncthreads();

    // ---- mainloop: 4 k-steps of 16, 3 split-combos each
#pragma unroll
    for (int ks = 0; ks < 4; ks++) {
        const int kb = ks * 8;
        unsigned Ah[2][4], Al[2][4];
#pragma unroll
        for (int mt = 0; mt < 2; mt++) {
            int r = (wm * 32 + mt * 16 + g) * QH_STR;
            Ah[mt][0] = Qh[r + kb + tg];
            Ah[mt][1] = Qh[r + 8 * QH_STR + kb + tg];
            Ah[mt][2] = Qh[r + kb + tg + 4];
            Ah[mt][3] = Qh[r + 8 * QH_STR + kb + tg + 4];
            Al[mt][0] = Ql[r + kb + tg];
            Al[mt][1] = Ql[r + 8 * QH_STR + kb + tg];
            Al[mt][2] = Ql[r + kb + tg + 4];
            Al[mt][3] = Ql[r + 8 * QH_STR + kb + tg + 4];
        }
#pragma unroll
        for (int nt = 0; nt < 8; nt++) {
            const int n = wn * 64 + nt * 8 + g;
            unsigned bh2[2], bl2[2];
            bh2[0] = Kh[(kb + tg) * KP_STR + n];
            bh2[1] = Kh[(kb + tg + 4) * KP_STR + n];
            bl2[0] = Kl[(kb + tg) * KP_STR + n];
            bl2[1] = Kl[(kb + tg + 4) * KP_STR + n];
#pragma unroll
            for (int mt = 0; mt < 2; mt++) {
                mma_bf16(acc[mt][nt], Ah[mt], bh2);
                mma_bf16(acc[mt][nt], Ah[mt], bl2);
                mma_bf16(acc[mt][nt], Al[mt], bh2);
            }
        }
    }

    // ---- epilogue: exp, streaming store, deterministic partial row sums
    float rs[2][2] = {{0.f, 0.f}, {0.f, 0.f}};
#pragma unroll
    for (int mt = 0; mt < 2; mt++) {
        const int r0 = wm * 32 + mt * 16 + g;
        float* base0 = attn + ((size_t)bh * SEQ + qt + r0) * SEQ + kt + wn * 64 + tg * 2;
        float* base1 = base0 + (size_t)8 * SEQ;
#pragma unroll
        for (int nt = 0; nt < 8; nt++) {
            float e0 = __expf(acc[mt][nt][0] * SCALE + dec2[nt].x);
            float e1 = __expf(acc[mt][nt][1] * SCALE + dec2[nt].y);
            float e2 = __expf(acc[mt][nt][2] * SCALE + dec2[nt].x);
            float e3 = __expf(acc[mt][nt][3] * SCALE + dec2[nt].y);
            float2 v0; v0.x = e0; v0.y = e1;
            float2 v1; v1.x = e2; v1.y = e3;
            __stcs((float2*)(base0 + nt * 8), v0);
            __stcs((float2*)(base1 + nt * 8), v1);
            rs[mt][0] += e0 + e1;
            rs[mt][1] += e2 + e3;
        }
    }
#pragma unroll
    for (int off = 1; off <= 2; off <<= 1) {
#pragma unroll
        for (int mt = 0; mt < 2; mt++) {
            rs[mt][0] += __shfl_xor_sync(0xffffffffu, rs[mt][0], off);
            rs[mt][1] += __shfl_xor_sync(0xffffffffu, rs[mt][1], off);
        }
    }
    if (tg == 0) {
#pragma unroll
        for (int mt = 0; mt < 2; mt++) {
            rowpart[wn * 128 + wm * 32 + mt * 16 + g]     = rs[mt][0];
            rowpart[wn * 128 + wm * 32 + mt * 16 + g + 8] = rs[mt][1];
        }
    }
    __syncthreads();
    if (tid < 128)
        g_psum[((size_t)bh * SEQ + qt + tid) * KTILES + blockIdx.x] =
            rowpart[tid] + rowpart[128 + tid];
}

// ============================================================================
// Row-sum reduce: g_inv[row] = 1 / sum over 16 partials. 65536 rows.
// ============================================================================
__global__ __launch_bounds__(256) void rowsum_kernel()
{
    const int r = blockIdx.x * 256 + threadIdx.x;
    const float4* p = (const float4*)(g_psum + (size_t)r * KTILES);
    float4 a = p[0], bq = p[1], c = p[2], d = p[3];
    float s = ((a.x + a.y) + (a.z + a.w)) + ((bq.x + bq.y) + (bq.z + bq.w))
            + ((c.x + c.y) + (c.z + c.w)) + ((d.x + d.y) + (d.z + d.w));
    g_inv[r] = 1.0f / s;
}

// ============================================================================
// PV (tensor cores, bf16x3 split) + normalize: reads e (streaming), computes
// p = e * inv[row] in the loader, writes p back to attn (final probs), splits
// p/V to bf16 hi/lo in smem, accumulates out = P @ V with mma.
// 128q x 64d tile per block, 128 threads = 4 warps stacked on q.
// ============================================================================
__global__ __launch_bounds__(128) void pv_tc(float* attn)
{
    extern __shared__ __align__(16) unsigned dsm[];
    unsigned* Ph = dsm;                    // [128][QH_STR]
    unsigned* Pl = Ph + 128 * QH_STR;
    unsigned* Vh = Pl + 128 * QH_STR;      // [32][VP_STR] packed k-pairs
    unsigned* Vl = Vh + 32 * VP_STR;

    const int tid = threadIdx.x;
    const int bh  = blockIdx.y;
    const int b   = bh >> 3;
    const int h   = bh & 7;
    const int qt  = blockIdx.x * 128;

    float* Prow = attn + ((size_t)bh * SEQ + qt + tid) * SEQ;
    const float inv = g_inv[(size_t)bh * SEQ + qt + tid];
    const float* Vg = g_qkv + (size_t)b * SEQ * QKVW + 2 * INNER + h * DH;

    const int lane = tid & 31, w = tid >> 5;
    const int g = lane >> 2, tg = lane & 3;
    const int vkp  = tid >> 2;           // 0..31 (V k-pair row)
    const int vcs  = (tid & 3) * 16;     // 0,16,32,48 (V col segment)

    float acc[2][8][4];
#pragma unroll
    for (int mt = 0; mt < 2; mt++)
#pragma unroll
        for (int nt = 0; nt < 8; nt++)
#pragma unroll
            for (int c = 0; c < 4; c++) acc[mt][nt][c] = 0.f;

    for (int k0 = 0; k0 < SEQ; k0 += 64) {
        __syncthreads();   // previous mma reads done before overwriting smem

        // ---- P: load e, normalize, write back, split to smem (1 row/thread)
#pragma unroll
        for (int c16 = 0; c16 < 16; c16++) {
            const int c = c16 * 4;
            float4 e4 = __ldcs((const float4*)(Prow + k0 + c));
            e4.x *= inv; e4.y *= inv; e4.z *= inv; e4.w *= inv;
            __stcs((float4*)(Prow + k0 + c), e4);
            float hx = bhi(e4.x), hy = bhi(e4.y), hz = bhi(e4.z), hw = bhi(e4.w);
            const int pi = tid * QH_STR + c / 2;
            Ph[pi + 0] = pack2(hx, hy);
            Ph[pi + 1] = pack2(hz, hw);
            Pl[pi + 0] = pack2(e4.x - hx, e4.y - hy);
            Pl[pi + 1] = pack2(e4.z - hz, e4.w - hw);
        }
        // ---- V: load 64x64 chunk, pack k-pairs
#pragma unroll
        for (int j = 0; j < 4; j++) {
            const int c = vcs + j * 4;
            float4 v0 = *(const float4*)(Vg + (size_t)(k0 + 2 * vkp) * QKVW + c);
            float4 v1 = *(const float4*)(Vg + (size_t)(k0 + 2 * vkp + 1) * QKVW + c);
            float h0x = bhi(v0.x), h0y = bhi(v0.y), h0z = bhi(v0.z), h0w = bhi(v0.w);
            float h1x = bhi(v1.x), h1y = bhi(v1.y), h1z = bhi(v1.z), h1w = bhi(v1.w);
            const int vi = vkp * VP_STR + c;
            Vh[vi + 0] = pack2(h0x, h1x);
            Vh[vi + 1] = pack2(h0y, h1y);
            Vh[vi + 2] = pack2(h0z, h1z);
            Vh[vi + 3] = pack2(h0w, h1w);
            Vl[vi + 0] = pack2(v0.x - h0x, v1.x - h1x);
            Vl[vi + 1] = pack2(v0.y - h0y, v1.y - h1y);
            Vl[vi + 2] = pack2(v0.z - h0z, v1.z - h1z);
            Vl[vi + 3] = pack2(v0.w - h0w, v1.w - h1w);
        }
        __syncthreads();

        // ---- mma: 4 k-steps of 16
#pragma unroll
        for (int ks = 0; ks < 4; ks++) {
            const int kb = ks * 8;
            unsigned Ah[2][4], Al[2][4];
#pragma unroll
            for (int mt = 0; mt < 2; mt++) {
                int r = (w * 32 + mt * 16 + g) * QH_STR;
                Ah[mt][0] = Ph[r + kb + tg];
                Ah[mt][1] = Ph[r + 8 * QH_STR + kb + tg];
                Ah[mt][2] = Ph[r + kb + tg + 4];
                Ah[mt][3] = Ph[r + 8 * QH_STR + kb + tg + 4];
                Al[mt][0] = Pl[r + kb + tg];
                Al[mt][1] = Pl[r + 8 * QH_STR + kb + tg];
                Al[mt][2] = Pl[r + kb + tg + 4];
                Al[mt][3] = Pl[r + 8 * QH_STR + kb + tg + 4];
            }
#pragma unroll
            for (int nt = 0; nt < 8; nt++) {
                const int n = nt * 8 + g;
                unsigned bh2[2], bl2[2];
                bh2[0] = Vh[(kb + tg) * VP_STR + n];
                bh2[1] = Vh[(kb + tg + 4) * VP_STR + n];
                bl2[0] = Vl[(kb + tg) * VP_STR + n];
                bl2[1] = Vl[(kb + tg + 4) * VP_STR + n];
#pragma unroll
                for (int mt = 0; mt < 2; mt++) {
                    mma_bf16(acc[mt][nt], Ah[mt], bh2);
                    mma_bf16(acc[mt][nt], Ah[mt], bl2);
                    mma_bf16(acc[mt][nt], Al[mt], bh2);
                }
            }
        }
    }

    // ---- epilogue: write g_av
#pragma unroll
    for (int mt = 0; mt < 2; mt++) {
        const int r0 = w * 32 + mt * 16 + g;
        float* o0 = g_av + ((size_t)b * SEQ + qt + r0) * INNER + h * DH + tg * 2;
        float* o1 = o0 + (size_t)8 * INNER;
#pragma unroll
        for (int nt = 0; nt < 8; nt++) {
            float2 v0; v0.x = acc[mt][nt][0]; v0.y = acc[mt][nt][1];
            float2 v1; v1.x = acc[mt][nt][2]; v1.y = acc[mt][nt][3];
            *(float2*)(o0 + nt * 8) = v0;
            *(float2*)(o1 + nt * 8) = v1;
        }
    }
}

// ============================================================================
// LayerNorm over last dim 512. One 256-thread block per row.
// ============================================================================
__global__ __launch_bounds__(256) void layernorm_kernel(
    const float* __restrict__ gamma, const float* __restrict__ beta,
    float* __restrict__ out)
{
    __shared__ float rs[8], rss[8];
    __shared__ float bmu, brstd;
    const size_t row = blockIdx.x;
    const float* p = g_u + row * DMODEL;
    const int tid = threadIdx.x;

    float x0 = p[tid], x1 = p[tid + 256];
    float s  = x0 + x1;
    float ss = x0 * x0 + x1 * x1;
#pragma unroll
    for (int o = 16; o; o >>= 1) {
        s  += __shfl_xor_sync(0xffffffffu, s, o);
        ss += __shfl_xor_sync(0xffffffffu, ss, o);
    }
    if ((tid & 31) == 0) { rs[tid >> 5] = s; rss[tid >> 5] = ss; }
    __syncthreads();
    if (tid == 0) {
        float ts = 0.f, tss = 0.f;
#pragma unroll
        for (int i = 0; i < 8; i++) { ts += rs[i]; tss += rss[i]; }
        float mu  = ts * (1.0f / DMODEL);
        float var = tss * (1.0f / DMODEL) - mu * mu;
        bmu = mu;
        brstd = rsqrtf(var + LN_EPS);
    }
    __syncthreads();
    const float mu = bmu, r = brstd;
    out[row * DMODEL + tid]       = (x0 - mu) * r * gamma[tid]       + beta[tid];
    out[row * DMODEL + tid + 256] = (x1 - mu) * r * gamma[tid + 256] + beta[tid + 256];
}

// ============================================================================
// Launcher
// ============================================================================
extern "C" void kernel_launch(void* const* d_in, const int* in_sizes, int n_in,
                              void* d_out, int out_size)
{
    (void)in_sizes; (void)n_in; (void)out_size;
    const float* x       = (const float*)d_in[0];
    const float* w_qkv   = (const float*)d_in[1];
    const float* w_unify = (const float*)d_in[2];
    const float* b_unify = (const float*)d_in[3];
    const float* ln_g    = (const float*)d_in[4];
    const float* ln_b    = (const float*)d_in[5];

    float* out_ln   = (float*)d_out;
    float* out_attn = out_ln + (size_t)BB * SEQ * DMODEL;

    float *qkv_p, *av_p, *u_p;
    cudaGetSymbolAddress((void**)&qkv_p, g_qkv);
    cudaGetSymbolAddress((void**)&av_p,  g_av);
    cudaGetSymbolAddress((void**)&u_p,   g_u);

    // opt-in to >48KB dynamic smem (idempotent; not a stream op, capture-safe)
    cudaFuncSetAttribute(scores_tc, cudaFuncAttributeMaxDynamicSharedMemorySize,
                         SC_SMEM_BYTES);
    cudaFuncSetAttribute(pv_tc, cudaFuncAttributeMaxDynamicSharedMemorySize,
                         PV_SMEM_BYTES);

    const int M = BB * SEQ;  // 8192

    // 1) qkv = x @ w_qkv
    sgemm_nn<<<dim3(QKVW / 128, M / 128), 256>>>(x, w_qkv, nullptr, qkv_p,
                                                 M, QKVW, DMODEL);
    // 2) e = exp(scores) -> attn region; partial row sums -> g_psum
    scores_tc<<<dim3(SEQ / 128, SEQ / 128, BB * HEADS), 256, SC_SMEM_BYTES>>>(out_attn);
    // 3) g_inv[row] = 1/sum
    rowsum_kernel<<<NROWS / 256, 256>>>();
    // 4) pv: normalize p into attn + av = p @ v  (tensor cores)
    pv_tc<<<dim3(SEQ / 128, BB * HEADS), 128, PV_SMEM_BYTES>>>(out_attn);
    // 5) unify: u = av @ w_unify + b_unify
    sgemm_nn<<<dim3(DMODEL / 128, M / 128), 256>>>(av_p, w_unify, b_unify, u_p,
                                                   M, DMODEL, INNER);
    // 6) layernorm -> ln region of d_out
    layernorm_kernel<<<M, 256>>>(ln_g, ln_b, out_ln);
}